// round 16
// baseline (speedup 1.0000x reference)
#include <cuda_runtime.h>
#include <math.h>
#include <stdint.h>

// Problem constants (match reference setup_inputs)
#define DIMF     2048
#define KIDS     8
#define P        256
#define HALF     2048
#define MARGIN   1.0f

#define THREADS  256
#define GROUP    16                    // rows per identity (2*K)
#define CHUNK    512                   // K floats per chunk
#define NCHUNK   (DIMF / CHUNK)        // 4
#define CH_O     (CHUNK / 8)           // 64 octs (32B units) per row per chunk
#define STRIDE_F 516                   // padded smem row stride (floats)
#define STRIDE_F4 (STRIDE_F / 4)       // 129
#define BUF_F4   (GROUP * STRIDE_F4)   // 2064 float4 per buffer
#define SMEM_BYTES (2 * BUF_F4 * 16)   // 66048 (double buffer)

// D(16x8) += A(16x8) * B(8x8), tf32. Gram trick: B fragments are A fragments.
#define MMA_TF32(d, a0, a1, a2, a3, b0, b1)                                \
    asm volatile(                                                          \
        "mma.sync.aligned.m16n8k8.row.col.f32.tf32.tf32.f32 "              \
        "{%0,%1,%2,%3}, {%4,%5,%6,%7}, {%8,%9}, {%0,%1,%2,%3};"            \
        : "+f"(d[0]), "+f"(d[1]), "+f"(d[2]), "+f"(d[3])                   \
        : "r"(a0), "r"(a1), "r"(a2), "r"(a3), "r"(b0), "r"(b1))

// L2-persistent 32-byte load (sm_103 requires v4.b64 with L2::evict_last).
__device__ __forceinline__ ulonglong4 ldg_el32(const void* p) {
    ulonglong4 v;
    asm volatile("ld.global.nc.L2::evict_last.v4.b64 {%0,%1,%2,%3}, [%4];"
                 : "=l"(v.x), "=l"(v.y), "=l"(v.z), "=l"(v.w) : "l"(p));
    return v;
}

__global__ __launch_bounds__(THREADS, 2)
void wloss_kernel(const float* __restrict__ x, float* __restrict__ out)
{
    extern __shared__ float smf[];               // [2][16][STRIDE_F]
    float4* smf4 = reinterpret_cast<float4*>(smf);
    __shared__ float gram[GROUP][GROUP];

    const int p    = blockIdx.x;                 // identity
    const int tid  = threadIdx.x;
    const int w    = tid >> 5;                   // warp 0..7 (K split)
    const int lane = tid & 31;

    if (tid < GROUP * GROUP)
        gram[tid >> 4][tid & 15] = 0.0f;

    // staging: 4 x 32B loads per thread per chunk (32 KB / 256 threads)
    ulonglong4 ra[4], rb[4];
    auto ldg_chunk = [&](ulonglong4* r, int ch) {
        #pragma unroll
        for (int j = 0; j < 4; j++) {
            int i   = j * THREADS + tid;         // 0..1023
            int row = i >> 6;                    // 0..15
            int c8  = i & (CH_O - 1);            // 32B unit within row chunk
            int grow = (row < KIDS) ? (p * KIDS + row)
                                    : (HALF + p * KIDS + (row - KIDS));
            const char* src = (const char*)x
                + ((size_t)grow * DIMF + (size_t)ch * CHUNK) * 4 + c8 * 32;
            r[j] = ldg_el32(src);
        }
    };
    auto sts_chunk = [&](const ulonglong4* r, int b) {
        #pragma unroll
        for (int j = 0; j < 4; j++) {
            int i   = j * THREADS + tid;
            int row = i >> 6;
            int c8  = i & (CH_O - 1);
            float4* dst = &smf4[b * BUF_F4 + row * STRIDE_F4 + 2 * c8];
            ulonglong2 lo = {r[j].x, r[j].y};
            ulonglong2 hi = {r[j].z, r[j].w};
            dst[0] = *reinterpret_cast<const float4*>(&lo);
            dst[1] = *reinterpret_cast<const float4*>(&hi);
        }
    };

    // MMA fragment indexing
    const int fr = lane >> 2;                    // fragment row 0..7
    const int ft = lane & 3;                     // fragment k 0..3
    float d1[4] = {0.f, 0.f, 0.f, 0.f};          // cols 0..7
    float d2[4] = {0.f, 0.f, 0.f, 0.f};          // cols 8..15

    auto compute = [&](int b) {                  // warp w: K-slab [w*64,+64)
        const float* b0p = smf + b * (BUF_F4 * 4) + fr * STRIDE_F + w * 64 + ft;
        const float* b1p = b0p + 8 * STRIDE_F;
        #pragma unroll
        for (int s = 0; s < 8; s++) {
            uint32_t a0 = __float_as_uint(b0p[s * 8]);
            uint32_t a2 = __float_as_uint(b0p[s * 8 + 4]);
            uint32_t a1 = __float_as_uint(b1p[s * 8]);
            uint32_t a3 = __float_as_uint(b1p[s * 8 + 4]);
            MMA_TF32(d1, a0, a1, a2, a3, a0, a2);   // B = rows 0..7
            MMA_TF32(d2, a0, a1, a2, a3, a1, a3);   // B = rows 8..15
        }
    };

    // ---- pipelined stream: regs hold chunk+1/+2 while smem holds chunk ----
    ldg_chunk(ra, 0);
    ldg_chunk(rb, 1);
    sts_chunk(ra, 0);
    __syncthreads();

    #pragma unroll
    for (int ch = 0; ch < NCHUNK; ch++) {
        compute(ch & 1);
        if (ch + 1 < NCHUNK)
            sts_chunk((ch & 1) ? ra : rb, (ch + 1) & 1);   // chunk ch+1
        if (ch + 2 < NCHUNK)
            ldg_chunk((ch & 1) ? rb : ra, ch + 2);         // refill freed regs
        __syncthreads();
    }

    // ---- reduce 8 warps' partial grams into smem ----
    {
        const int rr = lane >> 2;
        const int cc = 2 * (lane & 3);
        atomicAdd(&gram[rr][cc],             d1[0]);
        atomicAdd(&gram[rr][cc + 1],         d1[1]);
        atomicAdd(&gram[rr + 8][cc],         d1[2]);
        atomicAdd(&gram[rr + 8][cc + 1],     d1[3]);
        atomicAdd(&gram[rr][8 + cc],         d2[0]);
        atomicAdd(&gram[rr][8 + cc + 1],     d2[1]);
        atomicAdd(&gram[rr + 8][8 + cc],     d2[2]);
        atomicAdd(&gram[rr + 8][8 + cc + 1], d2[3]);
    }
    __syncthreads();

    // ---- mins + loss (warp 0; diag of gram == squared norms) ----
    if (w == 0) {
        const int r = lane & 15;
        float inv = 1.0f / (sqrtf(gram[r][r]) + 1e-10f);
        float minf = INFINITY, mins = INFINITY;
        #pragma unroll
        for (int c = 0; c < GROUP; c++) {
            float invc = __shfl_sync(0xffffffffu, inv, c);
            float v = gram[r][c] * inv * invc;
            if (c < KIDS) minf = fminf(minf, v);
            else          mins = fminf(mins, v);
        }
        float li = fmaxf(MARGIN - minf, 0.0f) + fmaxf(MARGIN - mins, 0.0f);
        if (lane >= 16) li = 0.0f;
        #pragma unroll
        for (int o = 16; o; o >>= 1)
            li += __shfl_xor_sync(0xffffffffu, li, o);
        if (lane == 0)
            atomicAdd(out, li);
    }
}

extern "C" void kernel_launch(void* const* d_in, const int* in_sizes, int n_in,
                              void* d_out, int out_size)
{
    const float* x = (const float*)d_in[0];
    float* out = (float*)d_out;

    cudaMemsetAsync(out, 0, sizeof(float), 0);

    static bool attr_set = false;
    if (!attr_set) {
        cudaFuncSetAttribute(wloss_kernel,
                             cudaFuncAttributeMaxDynamicSharedMemorySize,
                             SMEM_BYTES);
        attr_set = true;
    }

    wloss_kernel<<<P, THREADS, SMEM_BYTES>>>(x, out);
}